// round 8
// baseline (speedup 1.0000x reference)
#include <cuda_runtime.h>
#include <cstdint>

// ---------------------------------------------------------------------------
// MLGRUCell via exact bf16 tensor-core path (HMMA m16n8k16):
//   quantized activations are exact ints in [-128,127]; sign weights {-1,0,+1}
//   -> both exact in bf16, K=128 dot exact in fp32 accum.
// Gates: sigmoid(y)=0.5*tanh(y/2)+0.5 via tanh.approx.f32.
// B packed with a column permutation so each thread owns 4 contiguous output
// columns -> float4 epilogue.
// R8: L1-pinned B (evict_last), streaming x/hprev/out (evict_first / .cs),
//     hprev double-buffered across chunks.
// ---------------------------------------------------------------------------

// B fragments bf16: [mat(3)][ch(8)][kt(8)][lane(32)] -> uint4
//  .x/.y = b0/b1 of even (permuted) tile, .z/.w = odd tile.
//  Tile n-index j maps to actual column: ch*16 + (j>>1)*4 + 2*s + (j&1).
__device__ uint4 g_wfrag[3 * 8 * 8 * 32];

__device__ __forceinline__ unsigned sgn_bf16(float v) {
    return v > 0.f ? 0x3F80u : (v < 0.f ? 0xBF80u : 0u);
}

__global__ void prep_kernel(const float* __restrict__ Wf,
                            const float* __restrict__ Wc,
                            const float* __restrict__ Wg) {
    int idx = blockIdx.x * blockDim.x + threadIdx.x;
    if (idx >= 3 * 8 * 8 * 32) return;
    int lane = idx & 31;
    int kt   = (idx >> 5) & 7;
    int ch   = (idx >> 8) & 7;
    int mat  = idx >> 11;
    const float* W = (mat == 0) ? Wf : ((mat == 1) ? Wc : Wg);
    int g = lane >> 2, tig = lane & 3;
    int ne = ch * 16 + (g >> 1) * 4 + (g & 1);      // s=0
    int no = ne + 2;                                 // s=1
    int k0 = kt * 16 + tig * 2;
    uint4 r;
    // B[k][n] = sign(W[n][k]); W row-major [hidden=128][in=128]
    r.x = sgn_bf16(W[ne * 128 + k0])     | (sgn_bf16(W[ne * 128 + k0 + 1]) << 16);
    r.y = sgn_bf16(W[ne * 128 + k0 + 8]) | (sgn_bf16(W[ne * 128 + k0 + 9]) << 16);
    r.z = sgn_bf16(W[no * 128 + k0])     | (sgn_bf16(W[no * 128 + k0 + 1]) << 16);
    r.w = sgn_bf16(W[no * 128 + k0 + 8]) | (sgn_bf16(W[no * 128 + k0 + 9]) << 16);
    g_wfrag[idx] = r;
}

#define MMA_OP(D, A, b0, b1)                                                   \
    asm volatile(                                                              \
        "mma.sync.aligned.m16n8k16.row.col.f32.bf16.bf16.f32 "                 \
        "{%0,%1,%2,%3}, {%4,%5,%6,%7}, {%8,%9}, {%0,%1,%2,%3};\n"              \
        : "+f"(D[0]), "+f"(D[1]), "+f"(D[2]), "+f"(D[3])                       \
        : "r"(A.x), "r"(A.y), "r"(A.z), "r"(A.w), "r"(b0), "r"(b1))

__device__ __forceinline__ float tanh_ap(float x) {
    float y;
    asm("tanh.approx.f32 %0, %1;" : "=f"(y) : "f"(x));
    return y;
}
// B table: pin in L1 (read-only, reused 8x/warp, 4 warps/block, all blocks)
__device__ __forceinline__ uint4 ldg_keep(const uint4* p) {
    uint4 r;
    asm volatile("ld.global.nc.L1::evict_last.v4.u32 {%0,%1,%2,%3}, [%4];"
                 : "=r"(r.x), "=r"(r.y), "=r"(r.z), "=r"(r.w) : "l"(p));
    return r;
}
// streaming loads (x, hprev): never reused, don't evict B
__device__ __forceinline__ float4 ldg_stream(const float* p) {
    float4 r;
    asm volatile("ld.global.L1::evict_first.v4.f32 {%0,%1,%2,%3}, [%4];"
                 : "=f"(r.x), "=f"(r.y), "=f"(r.z), "=f"(r.w) : "l"(p));
    return r;
}
// streaming stores
__device__ __forceinline__ void stg_stream(float* p, float4 v) {
    asm volatile("st.global.cs.v4.f32 [%0], {%1,%2,%3,%4};"
                 :: "l"(p), "f"(v.x), "f"(v.y), "f"(v.z), "f"(v.w) : "memory");
}

__global__ __launch_bounds__(128, 4) void mlgru_kernel(
    const float* __restrict__ x, const float* __restrict__ hprev,
    const float* __restrict__ bf_, const float* __restrict__ bc_,
    const float* __restrict__ bg_, float* __restrict__ out, int half) {
    // A fragments: [mtile(8)][ktile(8)][lane(32)] -> uint4 (a0..a3)
    __shared__ uint4 qfrag[8][8][32];
    __shared__ float sinv[128];        // 0.5 * (maxabs/127) per row
    __shared__ float bias_sh[3][128];  // 0.5 * bias

    const int tid = threadIdx.x;
    const int w = tid >> 5, l = tid & 31;
    const int rowBlock = blockIdx.x * 128;

    bias_sh[0][tid] = 0.5f * bf_[tid];
    bias_sh[1][tid] = 0.5f * bc_[tid];
    bias_sh[2][tid] = 0.5f * bg_[tid];

    // ------------------- Phase 1: layernorm + quant -------------------
    {
        const int clb = (l & 7) * 4;
        #pragma unroll 2
        for (int it = 0; it < 8; it++) {
            const int r = w * 32 + it * 4 + (l >> 3);
            const float* xr = x + (rowBlock + r) * 128;
            float4 v[4];
            #pragma unroll
            for (int j = 0; j < 4; j++) v[j] = ldg_stream(xr + clb + 32 * j);

            float s1 = 0.f, s2 = 0.f;
            #pragma unroll
            for (int j = 0; j < 4; j++) {
                s1 += v[j].x + v[j].y + v[j].z + v[j].w;
                s2 += v[j].x * v[j].x + v[j].y * v[j].y +
                      v[j].z * v[j].z + v[j].w * v[j].w;
            }
            #pragma unroll
            for (int m = 1; m <= 4; m <<= 1) {
                s1 += __shfl_xor_sync(0xffffffffu, s1, m);
                s2 += __shfl_xor_sync(0xffffffffu, s2, m);
            }
            const float mean = s1 * (1.f / 128.f);
            const float var  = s2 * (1.f / 128.f) - mean * mean;
            const float rstd = 1.f / sqrtf(var + 1e-8f);

            float xn[16];
            float mx = 0.f;
            #pragma unroll
            for (int j = 0; j < 4; j++) {
                xn[4*j+0] = (v[j].x - mean) * rstd;
                xn[4*j+1] = (v[j].y - mean) * rstd;
                xn[4*j+2] = (v[j].z - mean) * rstd;
                xn[4*j+3] = (v[j].w - mean) * rstd;
                mx = fmaxf(mx, fabsf(xn[4*j+0]));
                mx = fmaxf(mx, fabsf(xn[4*j+1]));
                mx = fmaxf(mx, fabsf(xn[4*j+2]));
                mx = fmaxf(mx, fabsf(xn[4*j+3]));
            }
            #pragma unroll
            for (int m = 1; m <= 4; m <<= 1)
                mx = fmaxf(mx, __shfl_xor_sync(0xffffffffu, mx, m));

            const float s = 127.f / mx;
            if ((l & 7) == 0) sinv[r] = 0.5f * mx * (1.f / 127.f);

            const int mt = r >> 4, g8 = r & 7, hi2 = (r >> 3) & 1;
            #pragma unroll
            for (int j = 0; j < 4; j++) {
                float q[4];
                #pragma unroll
                for (int e = 0; e < 4; e++)
                    q[e] = fminf(fmaxf(rintf(s * xn[4*j+e]), -128.f), 127.f);
                #pragma unroll
                for (int p = 0; p < 2; p++) {
                    const int c0 = clb + 32 * j + 2 * p;
                    unsigned u = (__float_as_uint(q[2*p]) >> 16) |
                                 (__float_as_uint(q[2*p+1]) & 0xFFFF0000u);
                    const int kt  = c0 >> 4;
                    const int tg  = (c0 >> 1) & 3;
                    const int khi = (c0 >> 3) & 1;
                    ((unsigned*)&qfrag[mt][kt][(g8 << 2) | tg])[hi2 | (khi << 1)] = u;
                }
            }
        }
    }
    __syncthreads();

    // ------------------- Phase 2: 3 ternary MMAs + gates -------------------
    const int g = l >> 2, tig = l & 3;

    float sih[2][2];
    #pragma unroll
    for (int mt = 0; mt < 2; mt++)
        #pragma unroll
        for (int rh = 0; rh < 2; rh++)
            sih[mt][rh] = sinv[w * 32 + mt * 16 + g + rh * 8];

    const uint4* wbase = g_wfrag + l;
    const int rbase = rowBlock + w * 32 + g;   // + mt*16 + rh*8

    // hprev pipeline: preload chunk 0
    float4 hp[2][2];
    #pragma unroll
    for (int mt = 0; mt < 2; mt++)
        #pragma unroll
        for (int rh = 0; rh < 2; rh++)
            hp[mt][rh] = ldg_stream(hprev +
                (rbase + mt * 16 + rh * 8) * 128 + tig * 4);

    #pragma unroll 1
    for (int ch = 0; ch < 8; ch++) {    // 16 output columns per chunk
        const int cbase = ch * 16 + tig * 4;   // this chunk's 4 cols/thread

        // ---- prefetch NEXT chunk's hprev (consumed next iteration) ----
        const int cnext = (ch < 7 ? (ch + 1) * 16 : ch * 16) + tig * 4;
        float4 hpn[2][2];
        #pragma unroll
        for (int mt = 0; mt < 2; mt++)
            #pragma unroll
            for (int rh = 0; rh < 2; rh++)
                hpn[mt][rh] = ldg_stream(hprev +
                    (rbase + mt * 16 + rh * 8) * 128 + cnext);

        // acc[mat][mt][tile][4]
        float acc[3][2][2][4];
        #pragma unroll
        for (int m_ = 0; m_ < 3; m_++)
            #pragma unroll
            for (int a_ = 0; a_ < 2; a_++)
                #pragma unroll
                for (int t_ = 0; t_ < 2; t_++)
                    #pragma unroll
                    for (int e_ = 0; e_ < 4; e_++) acc[m_][a_][t_][e_] = 0.f;

        #pragma unroll
        for (int kt = 0; kt < 8; kt++) {
            const uint4 A0 = qfrag[2 * w][kt][l];
            const uint4 A1 = qfrag[2 * w + 1][kt][l];
            #pragma unroll
            for (int mat = 0; mat < 3; mat++) {
                const uint4 Bv = ldg_keep(wbase + ((mat * 8 + ch) * 8 + kt) * 32);
                MMA_OP(acc[mat][0][0], A0, Bv.x, Bv.y);
                MMA_OP(acc[mat][1][0], A1, Bv.x, Bv.y);
                MMA_OP(acc[mat][0][1], A0, Bv.z, Bv.w);
                MMA_OP(acc[mat][1][1], A1, Bv.z, Bv.w);
            }
        }

        // ---- epilogue: 4 contiguous cols/thread, float4 stores ----
        const float4 bF = *(const float4*)&bias_sh[0][cbase];
        const float4 bC = *(const float4*)&bias_sh[1][cbase];
        const float4 bG = *(const float4*)&bias_sh[2][cbase];
        const float bFv[4] = {bF.x, bF.y, bF.z, bF.w};
        const float bCv[4] = {bC.x, bC.y, bC.z, bC.w};
        const float bGv[4] = {bG.x, bG.y, bG.z, bG.w};

        #pragma unroll
        for (int mt = 0; mt < 2; mt++) {
            #pragma unroll
            for (int rh = 0; rh < 2; rh++) {
                const int row = rbase + mt * 16 + rh * 8;
                const float si = sih[mt][rh];
                const float hpv[4] = {hp[mt][rh].x, hp[mt][rh].y,
                                      hp[mt][rh].z, hp[mt][rh].w};
                float ov[4], hv[4];
                #pragma unroll
                for (int c = 0; c < 4; c++) {
                    const int t_ = c >> 1, e_ = rh * 2 + (c & 1);
                    const float zf = fmaf(acc[0][mt][t_][e_], si, bFv[c]);
                    const float zc = fmaf(acc[1][mt][t_][e_], si, bCv[c]);
                    const float zg = fmaf(acc[2][mt][t_][e_], si, bGv[c]);
                    const float f  = fmaf(0.5f, tanh_ap(zf), 0.5f);
                    const float gg = fmaf(0.5f, tanh_ap(zg), 0.5f);
                    const float sc = fmaf(0.5f, tanh_ap(zc), 0.5f);
                    const float cv = (zc + zc) * sc;      // silu
                    const float h  = fmaf(f, hpv[c] - cv, cv);
                    hv[c] = h;
                    ov[c] = gg * h;
                }
                stg_stream(out + row * 128 + cbase,
                           make_float4(ov[0], ov[1], ov[2], ov[3]));
                stg_stream(out + half + row * 128 + cbase,
                           make_float4(hv[0], hv[1], hv[2], hv[3]));
            }
        }

        // rotate hprev pipeline
        #pragma unroll
        for (int mt = 0; mt < 2; mt++)
            #pragma unroll
            for (int rh = 0; rh < 2; rh++)
                hp[mt][rh] = hpn[mt][rh];
    }
}

extern "C" void kernel_launch(void* const* d_in, const int* in_sizes, int n_in,
                              void* d_out, int out_size) {
    const float* x  = (const float*)d_in[0];
    const float* h  = (const float*)d_in[1];
    const float* Wf = (const float*)d_in[2];
    const float* Wc = (const float*)d_in[3];
    const float* Wg = (const float*)d_in[4];
    const float* bf = (const float*)d_in[5];
    const float* bc = (const float*)d_in[6];
    const float* bg = (const float*)d_in[7];
    float* out = (float*)d_out;

    prep_kernel<<<48, 128>>>(Wf, Wc, Wg);

    const int rows = in_sizes[0] / 128;      // 262144
    const int blocks = rows / 128;           // 2048
    const int half = out_size / 2;
    mlgru_kernel<<<blocks, 128>>>(x, h, bf, bc, bg, out, half);
}

// round 10
// speedup vs baseline: 1.0055x; 1.0055x over previous
#include <cuda_runtime.h>
#include <cstdint>

// ---------------------------------------------------------------------------
// MLGRUCell via exact bf16 tensor-core path (HMMA m16n8k16):
//   quantized activations are exact ints in [-128,127]; sign weights {-1,0,+1}
//   -> both exact in bf16, K=128 dot exact in fp32 accum.
// Gates: sigmoid(y)=0.5*tanh(y/2)+0.5 via tanh.approx.f32.
// B packed with a column permutation so each thread owns 4 contiguous output
// columns -> float4 epilogue.
// R10: persistent WARP-workers pulling 32-row tasks from a global atomic
//      counter (no wave-quantization tail, no block barriers at all).
// ---------------------------------------------------------------------------

// B fragments bf16: [mat(3)][ch(8)][kt(8)][lane(32)] -> uint4
//  .x/.y = b0/b1 of even (permuted) tile, .z/.w = odd tile.
//  Tile n-index j maps to actual column: ch*16 + (j>>1)*4 + 2*s + (j&1).
__device__ uint4 g_wfrag[3 * 8 * 8 * 32];
__device__ unsigned g_task;

__device__ __forceinline__ unsigned sgn_bf16(float v) {
    return v > 0.f ? 0x3F80u : (v < 0.f ? 0xBF80u : 0u);
}

__global__ void prep_kernel(const float* __restrict__ Wf,
                            const float* __restrict__ Wc,
                            const float* __restrict__ Wg) {
    int idx = blockIdx.x * blockDim.x + threadIdx.x;
    if (idx == 0) g_task = 0;                  // reset worker counter
    if (idx >= 3 * 8 * 8 * 32) return;
    int lane = idx & 31;
    int kt   = (idx >> 5) & 7;
    int ch   = (idx >> 8) & 7;
    int mat  = idx >> 11;
    const float* W = (mat == 0) ? Wf : ((mat == 1) ? Wc : Wg);
    int g = lane >> 2, tig = lane & 3;
    int ne = ch * 16 + (g >> 1) * 4 + (g & 1);      // s=0
    int no = ne + 2;                                 // s=1
    int k0 = kt * 16 + tig * 2;
    uint4 r;
    // B[k][n] = sign(W[n][k]); W row-major [hidden=128][in=128]
    r.x = sgn_bf16(W[ne * 128 + k0])     | (sgn_bf16(W[ne * 128 + k0 + 1]) << 16);
    r.y = sgn_bf16(W[ne * 128 + k0 + 8]) | (sgn_bf16(W[ne * 128 + k0 + 9]) << 16);
    r.z = sgn_bf16(W[no * 128 + k0])     | (sgn_bf16(W[no * 128 + k0 + 1]) << 16);
    r.w = sgn_bf16(W[no * 128 + k0 + 8]) | (sgn_bf16(W[no * 128 + k0 + 9]) << 16);
    g_wfrag[idx] = r;
}

#define MMA_OP(D, A, b0, b1)                                                   \
    asm volatile(                                                              \
        "mma.sync.aligned.m16n8k16.row.col.f32.bf16.bf16.f32 "                 \
        "{%0,%1,%2,%3}, {%4,%5,%6,%7}, {%8,%9}, {%0,%1,%2,%3};\n"              \
        : "+f"(D[0]), "+f"(D[1]), "+f"(D[2]), "+f"(D[3])                       \
        : "r"(A.x), "r"(A.y), "r"(A.z), "r"(A.w), "r"(b0), "r"(b1))

__device__ __forceinline__ float tanh_ap(float x) {
    float y;
    asm("tanh.approx.f32 %0, %1;" : "=f"(y) : "f"(x));
    return y;
}

#define NUM_TASKS 8192          // 262144 rows / 32 rows per task

__global__ __launch_bounds__(128, 4) void mlgru_kernel(
    const float* __restrict__ x, const float* __restrict__ hprev,
    const float* __restrict__ bf_, const float* __restrict__ bc_,
    const float* __restrict__ bg_, float* __restrict__ out, int half) {
    // Per-warp A fragments: [warp][mtile(2)][ktile(8)][lane(32)] -> uint4
    __shared__ uint4 qfrag[4][2][8][32];
    __shared__ float sinv[4][32];      // 0.5 * (maxabs/127), per warp-local row

    const int tid = threadIdx.x;
    const int w = tid >> 5, l = tid & 31;
    const int g = l >> 2, tig = l & 3;

    for (;;) {
        // ---- grab a 32-row task ----
        unsigned task;
        if (l == 0) task = atomicAdd(&g_task, 1u);
        task = __shfl_sync(0xffffffffu, task, 0);
        if (task >= NUM_TASKS) break;
        const int rowBase = (int)task * 32;

        // ------------------- Phase 1: layernorm + quant -------------------
        // 4 rows per iteration; lane l: row (l>>3), cols (l&7)*4 + 32j.
        {
            const int clb = (l & 7) * 4;
            #pragma unroll 2
            for (int it = 0; it < 8; it++) {
                const int rl = it * 4 + (l >> 3);       // local row 0..31
                const float* xr = x + (size_t)(rowBase + rl) * 128;
                float4 v[4];
                #pragma unroll
                for (int j = 0; j < 4; j++)
                    v[j] = *(const float4*)(xr + clb + 32 * j);

                float s1 = 0.f, s2 = 0.f;
                #pragma unroll
                for (int j = 0; j < 4; j++) {
                    s1 += v[j].x + v[j].y + v[j].z + v[j].w;
                    s2 += v[j].x * v[j].x + v[j].y * v[j].y +
                          v[j].z * v[j].z + v[j].w * v[j].w;
                }
                #pragma unroll
                for (int m = 1; m <= 4; m <<= 1) {
                    s1 += __shfl_xor_sync(0xffffffffu, s1, m);
                    s2 += __shfl_xor_sync(0xffffffffu, s2, m);
                }
                const float mean = s1 * (1.f / 128.f);
                const float var  = s2 * (1.f / 128.f) - mean * mean;
                const float rstd = 1.f / sqrtf(var + 1e-8f);

                float xn[16];
                float mx = 0.f;
                #pragma unroll
                for (int j = 0; j < 4; j++) {
                    xn[4*j+0] = (v[j].x - mean) * rstd;
                    xn[4*j+1] = (v[j].y - mean) * rstd;
                    xn[4*j+2] = (v[j].z - mean) * rstd;
                    xn[4*j+3] = (v[j].w - mean) * rstd;
                    mx = fmaxf(mx, fabsf(xn[4*j+0]));
                    mx = fmaxf(mx, fabsf(xn[4*j+1]));
                    mx = fmaxf(mx, fabsf(xn[4*j+2]));
                    mx = fmaxf(mx, fabsf(xn[4*j+3]));
                }
                #pragma unroll
                for (int m = 1; m <= 4; m <<= 1)
                    mx = fmaxf(mx, __shfl_xor_sync(0xffffffffu, mx, m));

                const float s = 127.f / mx;
                if ((l & 7) == 0) sinv[w][rl] = 0.5f * mx * (1.f / 127.f);

                const int mt = rl >> 4, g8 = rl & 7, hi2 = (rl >> 3) & 1;
                #pragma unroll
                for (int j = 0; j < 4; j++) {
                    float q[4];
                    #pragma unroll
                    for (int e = 0; e < 4; e++)
                        q[e] = fminf(fmaxf(rintf(s * xn[4*j+e]), -128.f), 127.f);
                    #pragma unroll
                    for (int p = 0; p < 2; p++) {
                        const int c0 = clb + 32 * j + 2 * p;
                        // bf16 of small ints == high 16 bits of fp32 (exact)
                        unsigned u = (__float_as_uint(q[2*p]) >> 16) |
                                     (__float_as_uint(q[2*p+1]) & 0xFFFF0000u);
                        const int kt  = c0 >> 4;
                        const int tg  = (c0 >> 1) & 3;
                        const int khi = (c0 >> 3) & 1;
                        ((unsigned*)&qfrag[w][mt][kt][(g8 << 2) | tg])
                            [hi2 | (khi << 1)] = u;
                    }
                }
            }
        }
        __syncwarp();

        // --------------- Phase 2: 3 ternary MMAs + gates ---------------
        float sih[2][2];
        #pragma unroll
        for (int mt = 0; mt < 2; mt++)
            #pragma unroll
            for (int rh = 0; rh < 2; rh++)
                sih[mt][rh] = sinv[w][mt * 16 + g + rh * 8];

        const uint4* wbase = g_wfrag + l;
        const int rbase = rowBase + g;     // + mt*16 + rh*8

        #pragma unroll 1
        for (int ch = 0; ch < 8; ch++) {   // 16 output columns per chunk
            const int cbase = ch * 16 + tig * 4;   // 4 contiguous cols/thread

            // ---- prefetch hprev (float4 per (mt,rh)) ----
            float4 hp[2][2];
            #pragma unroll
            for (int mt = 0; mt < 2; mt++)
                #pragma unroll
                for (int rh = 0; rh < 2; rh++)
                    hp[mt][rh] = *(const float4*)(hprev +
                        (size_t)(rbase + mt * 16 + rh * 8) * 128 + cbase);

            // acc[mat][mt][tile][4]
            float acc[3][2][2][4];
            #pragma unroll
            for (int m_ = 0; m_ < 3; m_++)
                #pragma unroll
                for (int a_ = 0; a_ < 2; a_++)
                    #pragma unroll
                    for (int t_ = 0; t_ < 2; t_++)
                        #pragma unroll
                        for (int e_ = 0; e_ < 4; e_++)
                            acc[m_][a_][t_][e_] = 0.f;

            #pragma unroll
            for (int kt = 0; kt < 8; kt++) {
                const uint4 A0 = qfrag[w][0][kt][l];
                const uint4 A1 = qfrag[w][1][kt][l];
                #pragma unroll
                for (int mat = 0; mat < 3; mat++) {
                    const uint4 Bv = wbase[((mat * 8 + ch) * 8 + kt) * 32];
                    MMA_OP(acc[mat][0][0], A0, Bv.x, Bv.y);
                    MMA_OP(acc[mat][1][0], A1, Bv.x, Bv.y);
                    MMA_OP(acc[mat][0][1], A0, Bv.z, Bv.w);
                    MMA_OP(acc[mat][1][1], A1, Bv.z, Bv.w);
                }
            }

            // ---- epilogue: 4 contiguous cols/thread, float4 stores ----
            const float4 bF = __ldg((const float4*)(bf_ + cbase));
            const float4 bC = __ldg((const float4*)(bc_ + cbase));
            const float4 bG = __ldg((const float4*)(bg_ + cbase));
            const float bFv[4] = {0.5f*bF.x, 0.5f*bF.y, 0.5f*bF.z, 0.5f*bF.w};
            const float bCv[4] = {0.5f*bC.x, 0.5f*bC.y, 0.5f*bC.z, 0.5f*bC.w};
            const float bGv[4] = {0.5f*bG.x, 0.5f*bG.y, 0.5f*bG.z, 0.5f*bG.w};

            #pragma unroll
            for (int mt = 0; mt < 2; mt++) {
                #pragma unroll
                for (int rh = 0; rh < 2; rh++) {
                    const int row = rbase + mt * 16 + rh * 8;
                    const float si = sih[mt][rh];
                    const float hpv[4] = {hp[mt][rh].x, hp[mt][rh].y,
                                          hp[mt][rh].z, hp[mt][rh].w};
                    float ov[4], hv[4];
                    #pragma unroll
                    for (int c = 0; c < 4; c++) {
                        const int t_ = c >> 1, e_ = rh * 2 + (c & 1);
                        const float zf = fmaf(acc[0][mt][t_][e_], si, bFv[c]);
                        const float zc = fmaf(acc[1][mt][t_][e_], si, bCv[c]);
                        const float zg = fmaf(acc[2][mt][t_][e_], si, bGv[c]);
                        const float f  = fmaf(0.5f, tanh_ap(zf), 0.5f);
                        const float gg = fmaf(0.5f, tanh_ap(zg), 0.5f);
                        const float sc = fmaf(0.5f, tanh_ap(zc), 0.5f);
                        const float cv = (zc + zc) * sc;      // silu
                        const float h  = fmaf(f, hpv[c] - cv, cv);
                        hv[c] = h;
                        ov[c] = gg * h;
                    }
                    *(float4*)(out + (size_t)row * 128 + cbase) =
                        make_float4(ov[0], ov[1], ov[2], ov[3]);
                    *(float4*)(out + (size_t)half + (size_t)row * 128 + cbase) =
                        make_float4(hv[0], hv[1], hv[2], hv[3]);
                }
            }
        }
        __syncwarp();
    }
}

extern "C" void kernel_launch(void* const* d_in, const int* in_sizes, int n_in,
                              void* d_out, int out_size) {
    const float* x  = (const float*)d_in[0];
    const float* h  = (const float*)d_in[1];
    const float* Wf = (const float*)d_in[2];
    const float* Wc = (const float*)d_in[3];
    const float* Wg = (const float*)d_in[4];
    const float* bf = (const float*)d_in[5];
    const float* bc = (const float*)d_in[6];
    const float* bg = (const float*)d_in[7];
    float* out = (float*)d_out;

    prep_kernel<<<48, 128>>>(Wf, Wc, Wg);

    const int half = out_size / 2;
    mlgru_kernel<<<592, 128>>>(x, h, bf, bc, bg, out, half);
}

// round 12
// speedup vs baseline: 1.0303x; 1.0247x over previous
#include <cuda_runtime.h>
#include <cstdint>

// ---------------------------------------------------------------------------
// MLGRUCell via exact bf16 tensor-core path (HMMA m16n8k16):
//   quantized activations are exact ints in [-127,127]; sign weights {-1,0,+1}
//   -> both exact in bf16, K=128 dot exact in fp32 accum.
// Gates: sigmoid(y)=0.5*tanh(y/2)+0.5 via tanh.approx.f32.
// B packed with a column permutation so each thread owns 4 contiguous output
// columns -> float4 epilogue.
// R11: instruction diet — packed f32x2 phase-1, clamp-free quant (|q|<=127 by
//      construction), PRMT bf16 packing, rsqrt/approx-div.
// ---------------------------------------------------------------------------

// B fragments bf16: [mat(3)][ch(8)][kt(8)][lane(32)] -> uint4
__device__ uint4 g_wfrag[3 * 8 * 8 * 32];

__device__ __forceinline__ unsigned sgn_bf16(float v) {
    return v > 0.f ? 0x3F80u : (v < 0.f ? 0xBF80u : 0u);
}

__global__ void prep_kernel(const float* __restrict__ Wf,
                            const float* __restrict__ Wc,
                            const float* __restrict__ Wg) {
    int idx = blockIdx.x * blockDim.x + threadIdx.x;
    if (idx >= 3 * 8 * 8 * 32) return;
    int lane = idx & 31;
    int kt   = (idx >> 5) & 7;
    int ch   = (idx >> 8) & 7;
    int mat  = idx >> 11;
    const float* W = (mat == 0) ? Wf : ((mat == 1) ? Wc : Wg);
    int g = lane >> 2, tig = lane & 3;
    int ne = ch * 16 + (g >> 1) * 4 + (g & 1);      // s=0
    int no = ne + 2;                                 // s=1
    int k0 = kt * 16 + tig * 2;
    uint4 r;
    // B[k][n] = sign(W[n][k]); W row-major [hidden=128][in=128]
    r.x = sgn_bf16(W[ne * 128 + k0])     | (sgn_bf16(W[ne * 128 + k0 + 1]) << 16);
    r.y = sgn_bf16(W[ne * 128 + k0 + 8]) | (sgn_bf16(W[ne * 128 + k0 + 9]) << 16);
    r.z = sgn_bf16(W[no * 128 + k0])     | (sgn_bf16(W[no * 128 + k0 + 1]) << 16);
    r.w = sgn_bf16(W[no * 128 + k0 + 8]) | (sgn_bf16(W[no * 128 + k0 + 9]) << 16);
    g_wfrag[idx] = r;
}

#define MMA_OP(D, A, b0, b1)                                                   \
    asm volatile(                                                              \
        "mma.sync.aligned.m16n8k16.row.col.f32.bf16.bf16.f32 "                 \
        "{%0,%1,%2,%3}, {%4,%5,%6,%7}, {%8,%9}, {%0,%1,%2,%3};\n"              \
        : "+f"(D[0]), "+f"(D[1]), "+f"(D[2]), "+f"(D[3])                       \
        : "r"(A.x), "r"(A.y), "r"(A.z), "r"(A.w), "r"(b0), "r"(b1))

__device__ __forceinline__ float tanh_ap(float x) {
    float y;
    asm("tanh.approx.f32 %0, %1;" : "=f"(y) : "f"(x));
    return y;
}

// ---- packed f32x2 helpers (sm_100+) ----
typedef unsigned long long u64t;
__device__ __forceinline__ u64t pk2(float x, float y) {
    u64t r; asm("mov.b64 %0, {%1, %2};" : "=l"(r) : "f"(x), "f"(y)); return r;
}
__device__ __forceinline__ float2 up2(u64t v) {
    float2 r; asm("mov.b64 {%0, %1}, %2;" : "=f"(r.x), "=f"(r.y) : "l"(v));
    return r;
}
__device__ __forceinline__ u64t fma2_(u64t a, u64t b, u64t c) {
    u64t d; asm("fma.rn.f32x2 %0, %1, %2, %3;" : "=l"(d) : "l"(a), "l"(b), "l"(c));
    return d;
}
__device__ __forceinline__ u64t add2_(u64t a, u64t b) {
    u64t d; asm("add.rn.f32x2 %0, %1, %2;" : "=l"(d) : "l"(a), "l"(b)); return d;
}
__device__ __forceinline__ u64t mul2_(u64t a, u64t b) {
    u64t d; asm("mul.rn.f32x2 %0, %1, %2;" : "=l"(d) : "l"(a), "l"(b)); return d;
}
__device__ __forceinline__ u64t abs2_(u64t a) {
    u64t d; asm("and.b64 %0, %1, %2;" : "=l"(d)
                : "l"(a), "l"(0x7FFFFFFF7FFFFFFFULL)); return d;
}

__global__ __launch_bounds__(128, 4) void mlgru_kernel(
    const float* __restrict__ x, const float* __restrict__ hprev,
    const float* __restrict__ bf_, const float* __restrict__ bc_,
    const float* __restrict__ bg_, float* __restrict__ out, int half) {
    // A fragments: [mtile(8)][ktile(8)][lane(32)] -> uint4 (a0..a3)
    __shared__ uint4 qfrag[8][8][32];
    __shared__ float sinv[128];        // 0.5 * (maxabs/127) per row
    __shared__ float bias_sh[3][128];  // 0.5 * bias

    const int tid = threadIdx.x;
    const int w = tid >> 5, l = tid & 31;
    const int rowBlock = blockIdx.x * 128;

    bias_sh[0][tid] = 0.5f * bf_[tid];
    bias_sh[1][tid] = 0.5f * bc_[tid];
    bias_sh[2][tid] = 0.5f * bg_[tid];

    // ------------------- Phase 1: layernorm + quant (packed) ----------------
    // 4 rows per iteration; lane l: row (l>>3), cols (l&7)*4 + 32j.
    {
        const int clb = (l & 7) * 4;
        #pragma unroll 2
        for (int it = 0; it < 8; it++) {
            const int r = w * 32 + it * 4 + (l >> 3);
            const float4* xr = (const float4*)(x + (size_t)(rowBlock + r) * 128);
            u64t vp[8];
            #pragma unroll
            for (int j = 0; j < 4; j++) {
                const float4 v = xr[(clb >> 2) + 8 * j];
                vp[2 * j]     = pk2(v.x, v.y);
                vp[2 * j + 1] = pk2(v.z, v.w);
            }

            // packed sums
            u64t s1p = add2_(add2_(add2_(vp[0], vp[1]), add2_(vp[2], vp[3])),
                             add2_(add2_(vp[4], vp[5]), add2_(vp[6], vp[7])));
            u64t s2p = mul2_(vp[0], vp[0]);
            #pragma unroll
            for (int k = 1; k < 8; k++) s2p = fma2_(vp[k], vp[k], s2p);
            float2 t1 = up2(s1p), t2 = up2(s2p);
            float s1 = t1.x + t1.y, s2 = t2.x + t2.y;

            #pragma unroll
            for (int m = 1; m <= 4; m <<= 1) {
                s1 += __shfl_xor_sync(0xffffffffu, s1, m);
                s2 += __shfl_xor_sync(0xffffffffu, s2, m);
            }
            const float mean = s1 * (1.f / 128.f);
            const float var  = s2 * (1.f / 128.f) - mean * mean;
            const float rstd = rsqrtf(var + 1e-8f);

            // packed normalize + abs-max
            const u64t rs2 = pk2(rstd, rstd);
            const u64t nm2 = pk2(-mean * rstd, -mean * rstd);
            float mx = 0.f;
            #pragma unroll
            for (int k = 0; k < 8; k++) {
                const float2 a = up2(abs2_(fma2_(vp[k], rs2, nm2)));
                mx = fmaxf(mx, fmaxf(a.x, a.y));
            }
            #pragma unroll
            for (int m = 1; m <= 4; m <<= 1)
                mx = fmaxf(mx, __shfl_xor_sync(0xffffffffu, mx, m));

            const float s = __fdividef(127.f, mx);
            if ((l & 7) == 0) sinv[r] = 0.5f * mx * (1.f / 127.f);

            // fused quant: q = rint((v - mean)*rstd*s); |q| <= 127 by
            // construction (s = 127/max|xn|), so no clamping needed.
            const float aa = rstd * s;
            const u64t aa2 = pk2(aa, aa);
            const u64t bb2 = pk2(-mean * aa, -mean * aa);

            const int mt = r >> 4, g8 = r & 7, hi2 = (r >> 3) & 1;
            #pragma unroll
            for (int j = 0; j < 4; j++) {
                #pragma unroll
                for (int p = 0; p < 2; p++) {
                    const float2 q = up2(fma2_(vp[2 * j + p], aa2, bb2));
                    // bf16 of small ints == high 16 bits of fp32 (exact);
                    // one PRMT packs both halves.
                    const unsigned u = __byte_perm(
                        __float_as_uint(rintf(q.x)),
                        __float_as_uint(rintf(q.y)), 0x7632);
                    const int c0  = clb + 32 * j + 2 * p;
                    const int kt  = c0 >> 4;
                    const int tg  = (c0 >> 1) & 3;
                    const int khi = (c0 >> 3) & 1;
                    ((unsigned*)&qfrag[mt][kt][(g8 << 2) | tg])[hi2 | (khi << 1)] = u;
                }
            }
        }
    }
    __syncthreads();

    // ------------------- Phase 2: 3 ternary MMAs + gates -------------------
    const int g = l >> 2, tig = l & 3;

    float sih[2][2];
    #pragma unroll
    for (int mt = 0; mt < 2; mt++)
        #pragma unroll
        for (int rh = 0; rh < 2; rh++)
            sih[mt][rh] = sinv[w * 32 + mt * 16 + g + rh * 8];

    const uint4* wbase = g_wfrag + l;
    const int rbase = rowBlock + w * 32 + g;   // + mt*16 + rh*8

    #pragma unroll 1
    for (int ch = 0; ch < 8; ch++) {    // 16 output columns per chunk
        const int cbase = ch * 16 + tig * 4;   // 4 contiguous cols per thread

        // ---- prefetch hprev (float4 per (mt,rh)) ----
        float4 hp[2][2];
        #pragma unroll
        for (int mt = 0; mt < 2; mt++)
            #pragma unroll
            for (int rh = 0; rh < 2; rh++)
                hp[mt][rh] = *(const float4*)(hprev +
                    (size_t)(rbase + mt * 16 + rh * 8) * 128 + cbase);

        // acc[mat][mt][tile][4]
        float acc[3][2][2][4];
        #pragma unroll
        for (int m_ = 0; m_ < 3; m_++)
            #pragma unroll
            for (int a_ = 0; a_ < 2; a_++)
                #pragma unroll
                for (int t_ = 0; t_ < 2; t_++)
                    #pragma unroll
                    for (int e_ = 0; e_ < 4; e_++) acc[m_][a_][t_][e_] = 0.f;

        #pragma unroll
        for (int kt = 0; kt < 8; kt++) {
            const uint4 A0 = qfrag[2 * w][kt][l];
            const uint4 A1 = qfrag[2 * w + 1][kt][l];
            #pragma unroll
            for (int mat = 0; mat < 3; mat++) {
                const uint4 Bv = wbase[((mat * 8 + ch) * 8 + kt) * 32];
                MMA_OP(acc[mat][0][0], A0, Bv.x, Bv.y);
                MMA_OP(acc[mat][1][0], A1, Bv.x, Bv.y);
                MMA_OP(acc[mat][0][1], A0, Bv.z, Bv.w);
                MMA_OP(acc[mat][1][1], A1, Bv.z, Bv.w);
            }
        }

        // ---- epilogue: 4 contiguous cols/thread, float4 stores ----
        const float4 bF = *(const float4*)&bias_sh[0][cbase];
        const float4 bC = *(const float4*)&bias_sh[1][cbase];
        const float4 bG = *(const float4*)&bias_sh[2][cbase];
        const float bFv[4] = {bF.x, bF.y, bF.z, bF.w};
        const float bCv[4] = {bC.x, bC.y, bC.z, bC.w};
        const float bGv[4] = {bG.x, bG.y, bG.z, bG.w};

        #pragma unroll
        for (int mt = 0; mt < 2; mt++) {
            #pragma unroll
            for (int rh = 0; rh < 2; rh++) {
                const int row = rbase + mt * 16 + rh * 8;
                const float si = sih[mt][rh];
                const float hpv[4] = {hp[mt][rh].x, hp[mt][rh].y,
                                      hp[mt][rh].z, hp[mt][rh].w};
                float ov[4], hv[4];
                #pragma unroll
                for (int c = 0; c < 4; c++) {
                    const int t_ = c >> 1, e_ = rh * 2 + (c & 1);
                    const float zf = fmaf(acc[0][mt][t_][e_], si, bFv[c]);
                    const float zc = fmaf(acc[1][mt][t_][e_], si, bCv[c]);
                    const float zg = fmaf(acc[2][mt][t_][e_], si, bGv[c]);
                    const float f  = fmaf(0.5f, tanh_ap(zf), 0.5f);
                    const float gg = fmaf(0.5f, tanh_ap(zg), 0.5f);
                    const float sc = fmaf(0.5f, tanh_ap(zc), 0.5f);
                    const float cv = (zc + zc) * sc;      // silu
                    const float h  = fmaf(f, hpv[c] - cv, cv);
                    hv[c] = h;
                    ov[c] = gg * h;
                }
                *(float4*)(out + (size_t)row * 128 + cbase) =
                    make_float4(ov[0], ov[1], ov[2], ov[3]);
                *(float4*)(out + (size_t)half + (size_t)row * 128 + cbase) =
                    make_float4(hv[0], hv[1], hv[2], hv[3]);
            }
        }
    }
}

extern "C" void kernel_launch(void* const* d_in, const int* in_sizes, int n_in,
                              void* d_out, int out_size) {
    const float* x  = (const float*)d_in[0];
    const float* h  = (const float*)d_in[1];
    const float* Wf = (const float*)d_in[2];
    const float* Wc = (const float*)d_in[3];
    const float* Wg = (const float*)d_in[4];
    const float* bf = (const float*)d_in[5];
    const float* bc = (const float*)d_in[6];
    const float* bg = (const float*)d_in[7];
    float* out = (float*)d_out;

    prep_kernel<<<48, 128>>>(Wf, Wc, Wg);

    const int rows = in_sizes[0] / 128;      // 262144
    const int blocks = rows / 128;           // 2048
    const int half = out_size / 2;
    mlgru_kernel<<<blocks, 128>>>(x, h, bf, bc, bg, out, half);
}